// round 9
// baseline (speedup 1.0000x reference)
#include <cuda_runtime.h>

#define NB 16
#define L 768
#define D 128
#define L3 256          // L / CLIP
#define KD 384          // CLIP * D
#define INV_T 0.08838834764831845f   // 1/sqrt(128)

// scratch (allocation-free rule: __device__ globals)
__device__ float g_Lb[NB * L3 * L3 + 512];

typedef unsigned long long u64;

__device__ __forceinline__ u64 pk2(float x, float y) {
    u64 r; asm("mov.b64 %0,{%1,%2};" : "=l"(r) : "f"(x), "f"(y)); return r;
}
__device__ __forceinline__ float2 upk2(u64 v) {
    float2 f; asm("mov.b64 {%0,%1},%2;" : "=f"(f.x), "=f"(f.y) : "l"(v)); return f;
}
#define FMA2(acc, a, b) \
    asm("fma.rn.f32x2 %0,%1,%2,%0;" : "+l"(acc) : "l"(a), "l"(b))

// ---------------------------------------------------------------------------
// Kernel 1: local block GEMM with fc-weight folding fused into the A loader.
// ---------------------------------------------------------------------------
__global__ __launch_bounds__(256) void lb_kernel(const float* __restrict__ q,
                                                 const float* __restrict__ k,
                                                 const float* __restrict__ fc_w,
                                                 const float* __restrict__ fc_b) {
    __shared__ float sA[64][65];
    __shared__ float sB[64][65];
    const int b  = blockIdx.z;
    const int i0 = blockIdx.y * 64;
    const int j0 = blockIdx.x * 64;
    const int tid = threadIdx.x;
    const int txn = tid & 15;    // n dim
    const int tym = tid >> 4;    // m dim

    float w[9];
    #pragma unroll
    for (int x = 0; x < 9; ++x) w[x] = __ldg(fc_w + x);

    const float* qb = q + (size_t)b * L * D;
    const float* kb = k + (size_t)b * L * D;   // (256, 384) view

    float acc[4][4] = {};

    for (int k0 = 0; k0 < KD; k0 += 64) {
        #pragma unroll
        for (int it = 0; it < 4; ++it) {
            int lin = tid + it * 256;
            int r  = lin >> 4;        // 0..63
            int c4 = lin & 15;        // 0..15
            int kcol = k0 + c4 * 4;
            int c = kcol >> 7;
            int d = kcol & 127;
            const float* qr = qb + (size_t)(3 * (i0 + r)) * D + d;
            float4 q0 = *(const float4*)qr;
            float4 q1 = *(const float4*)(qr + D);
            float4 q2 = *(const float4*)(qr + 2 * D);
            float w0 = w[c], w1 = w[3 + c], w2 = w[6 + c];
            sA[r][c4 * 4 + 0] = w0 * q0.x + w1 * q1.x + w2 * q2.x;
            sA[r][c4 * 4 + 1] = w0 * q0.y + w1 * q1.y + w2 * q2.y;
            sA[r][c4 * 4 + 2] = w0 * q0.z + w1 * q1.z + w2 * q2.z;
            sA[r][c4 * 4 + 3] = w0 * q0.w + w1 * q1.w + w2 * q2.w;
            float4 bv = *(const float4*)(kb + (size_t)(j0 + r) * KD + kcol);
            sB[r][c4 * 4 + 0] = bv.x; sB[r][c4 * 4 + 1] = bv.y;
            sB[r][c4 * 4 + 2] = bv.z; sB[r][c4 * 4 + 3] = bv.w;
        }
        __syncthreads();
        #pragma unroll 8
        for (int kk = 0; kk < 64; ++kk) {
            float a[4], bb[4];
            #pragma unroll
            for (int i = 0; i < 4; ++i) a[i]  = sA[tym * 4 + i][kk];
            #pragma unroll
            for (int j = 0; j < 4; ++j) bb[j] = sB[txn + 16 * j][kk];
            #pragma unroll
            for (int i = 0; i < 4; ++i)
                #pragma unroll
                for (int j = 0; j < 4; ++j) acc[i][j] += a[i] * bb[j];
        }
        __syncthreads();
    }

    const float bias = 128.0f * fc_b[0];
    float* Lbp = g_Lb + (size_t)b * L3 * L3;
    #pragma unroll
    for (int i = 0; i < 4; ++i)
        #pragma unroll
        for (int j = 0; j < 4; ++j)
            Lbp[(size_t)(i0 + tym * 4 + i) * L3 + (j0 + txn + 16 * j)] = acc[i][j] + bias;
}

// ---------------------------------------------------------------------------
// Kernel 2: fused attention, flash-style, packed f32x2 FMA, 4 CTAs/SM.
// One CTA = (batch b, 32 query rows). 128 threads (4 warps).
// K/V tile xor-swizzled at float4 granularity (no pad). sST is [m][n].
// SMEM: sQ[32][128] | sKVswz[64][128] | sST[32][64] = 57,344 B -> 4 CTAs/SM
// ---------------------------------------------------------------------------
#define CH 64
#define NCH 12
#define SM_Q    0
#define SM_KV   (32 * 128)
#define SM_ST   (32 * 128 + CH * 128)
#define SMEM_FLOATS (32 * 128 + CH * 128 + 32 * 64)   // 14336

__global__ __launch_bounds__(128, 4) void fused_attn_kernel(
    const float* __restrict__ q, const float* __restrict__ k,
    const float* __restrict__ v, float* __restrict__ out,
    float* __restrict__ attn) {
    extern __shared__ float smem[];
    float* sQ  = smem + SM_Q;    // [m][d], row stride 128
    float* sKV = smem + SM_KV;   // [n][d], row stride 128, f4-col xor (n&31)
    float* sST = smem + SM_ST;   // [m][n], row stride 64

    const int b  = blockIdx.y;
    const int m0 = blockIdx.x * 32;
    const int tid = threadIdx.x;
    const int tx = tid & 31;
    const int ty = tid >> 5;     // warp id 0..3, owns rows 8*ty..8*ty+7

    // ---- load q tile [m][d] ----
    #pragma unroll
    for (int it = 0; it < 8; ++it) {
        int lin = tid + it * 128;
        int m  = lin >> 5;       // 0..31
        int d4 = lin & 31;
        float4 qv = *(const float4*)(q + (size_t)((b * L + m0 + m) * D) + d4 * 4);
        *(float4*)(sQ + m * 128 + d4 * 4) = qv;
    }

    const float* Lbp = g_Lb + (size_t)b * L3 * L3;
    int qi[8];
    #pragma unroll
    for (int i = 0; i < 8; ++i) qi[i] = (m0 + ty * 8 + i) / 3;

    u64 oacc[8][2] = {};     // [m_i][dcol pair], dcols tx*4..tx*4+3
    float rsum[8] = {};

    for (int c = 0; c < NCH; ++c) {
        // ---- load K chunk (xor-swizzled) ----
        #pragma unroll
        for (int it = 0; it < 16; ++it) {
            int lin = tid + it * 128;
            int n  = lin >> 5;       // 0..63 (constant per warp per it)
            int d4 = lin & 31;
            float4 kv = *(const float4*)(k + (size_t)((b * L + c * CH + n) * D) + d4 * 4);
            *(float4*)(sKV + n * 128 + ((d4 ^ (n & 31)) << 2)) = kv;
        }
        __syncthreads();

        // ---- S = q @ k^T (m=8, j=2, d paired via f32x2) ----
        u64 acc[8][2] = {};
        #pragma unroll 2
        for (int g = 0; g < 32; ++g) {           // float4-col index
            int sw = (g ^ tx) << 2;
            ulonglong2 ka = *(const ulonglong2*)(sKV + (tx      ) * 128 + sw);
            ulonglong2 kc = *(const ulonglong2*)(sKV + (tx + 32 ) * 128 + sw);
            #pragma unroll
            for (int i = 0; i < 8; ++i) {
                ulonglong2 qp = *(const ulonglong2*)(sQ + (ty * 8 + i) * 128 + g * 4);
                FMA2(acc[i][0], qp.x, ka.x);
                FMA2(acc[i][0], qp.y, ka.y);
                FMA2(acc[i][1], qp.x, kc.x);
                FMA2(acc[i][1], qp.y, kc.y);
            }
        }

        // ---- epilogue: e = exp((lo+hi + Lb)/T); stash, write attn, rsum ----
        #pragma unroll
        for (int j = 0; j < 2; ++j) {
            int nl = tx + 32 * j;
            int n  = c * CH + nl;
            int kj = n / 3;
            float lb[8];
            #pragma unroll
            for (int i = 0; i < 8; ++i) lb[i] = __ldg(Lbp + (size_t)qi[i] * L3 + kj);
            #pragma unroll
            for (int i = 0; i < 8; ++i) {
                float2 a = upk2(acc[i][j]);
                float s = (a.x + a.y + lb[i]) * INV_T;
                float e = __expf(s);
                rsum[i] += e;
                sST[(ty * 8 + i) * 64 + nl] = e;
                attn[(size_t)(b * L + m0 + ty * 8 + i) * L + n] = e;  // unnorm
            }
        }
        __syncthreads();

        // ---- load V chunk (reuse sKV, xor-swizzled) ----
        #pragma unroll
        for (int it = 0; it < 16; ++it) {
            int lin = tid + it * 128;
            int n  = lin >> 5;
            int d4 = lin & 31;
            float4 vv = *(const float4*)(v + (size_t)((b * L + c * CH + n) * D) + d4 * 4);
            *(float4*)(sKV + n * 128 + ((d4 ^ (n & 31)) << 2)) = vv;
        }
        __syncthreads();

        // ---- O += e @ V (lane owns d-cols tx*4..tx*4+3 as 2 pairs) ----
        #pragma unroll 2
        for (int n = 0; n < CH; ++n) {
            ulonglong2 vv = *(const ulonglong2*)(sKV + n * 128 + ((tx ^ (n & 31)) << 2));
            const float* er = sST + ty * 8 * 64 + n;
            #pragma unroll
            for (int i = 0; i < 8; ++i) {
                float e = er[i * 64];              // broadcast
                u64 es = pk2(e, e);
                FMA2(oacc[i][0], es, vv.x);
                FMA2(oacc[i][1], es, vv.y);
            }
        }
        __syncthreads();
    }

    // ---- row sums -> inverses (lanes of this warp cover the full row) ----
    float inv[8];
    #pragma unroll
    for (int i = 0; i < 8; ++i) {
        float s = rsum[i];
        #pragma unroll
        for (int o = 16; o; o >>= 1) s += __shfl_xor_sync(0xffffffffu, s, o);
        inv[i] = 1.0f / s;
    }

    // ---- normalize attn strip in place (just-written -> L2 hits) ----
    #pragma unroll
    for (int i = 0; i < 8; ++i) {
        float* arow = attn + (size_t)(b * L + m0 + ty * 8 + i) * L;
        float iv = inv[i];
        #pragma unroll
        for (int t = 0; t < 6; ++t) {
            float4* p = (float4*)arow + tx + 32 * t;
            float4 vv = *p;
            vv.x *= iv; vv.y *= iv; vv.z *= iv; vv.w *= iv;
            *p = vv;
        }
    }

    // ---- normalized output (STG.128) ----
    #pragma unroll
    for (int i = 0; i < 8; ++i) {
        float* orow = out + (size_t)((b * L + m0 + ty * 8 + i) * D);
        float iv = inv[i];
        float2 p0 = upk2(oacc[i][0]);
        float2 p1 = upk2(oacc[i][1]);
        float4 o = make_float4(p0.x * iv, p0.y * iv, p1.x * iv, p1.y * iv);
        *(float4*)(orow + tx * 4) = o;
    }
}

// ---------------------------------------------------------------------------
extern "C" void kernel_launch(void* const* d_in, const int* in_sizes, int n_in,
                              void* d_out, int out_size) {
    const float* q    = (const float*)d_in[0];
    const float* k    = (const float*)d_in[1];
    const float* v    = (const float*)d_in[2];
    const float* fc_w = (const float*)d_in[3];
    const float* fc_b = (const float*)d_in[4];

    float* out  = (float*)d_out;
    float* attn = out + (size_t)NB * L * D;   // output first, then attn

    lb_kernel<<<dim3(4, 4, NB), 256>>>(q, k, fc_w, fc_b);

    const int smem_bytes = SMEM_FLOATS * sizeof(float);   // 57344
    cudaFuncSetAttribute(fused_attn_kernel,
                         cudaFuncAttributeMaxDynamicSharedMemorySize, smem_bytes);
    fused_attn_kernel<<<dim3(24, NB), 128, smem_bytes>>>(q, k, v, out, attn);
}

// round 10
// speedup vs baseline: 1.1532x; 1.1532x over previous
#include <cuda_runtime.h>

#define NB 16
#define L 768
#define D 128
#define L3 256          // L / CLIP
#define KD 384          // CLIP * D
#define INV_T 0.08838834764831845f   // 1/sqrt(128)

__device__ float g_Lb[NB * L3 * L3 + 512];

// ---- tf32 helpers -------------------------------------------------------
__device__ __forceinline__ unsigned cvt_tf32(float v) {
    unsigned r; asm("cvt.rna.tf32.f32 %0, %1;" : "=r"(r) : "f"(v)); return r;
}
struct HL { unsigned hi, lo; };
__device__ __forceinline__ HL split_tf32(float v) {
    HL h; h.hi = cvt_tf32(v);
    h.lo = cvt_tf32(v - __uint_as_float(h.hi));
    return h;
}
#define MMA(c, A0,A1,A2,A3, B0,B1) \
    asm("mma.sync.aligned.m16n8k8.row.col.f32.tf32.tf32.f32 " \
        "{%0,%1,%2,%3},{%4,%5,%6,%7},{%8,%9},{%0,%1,%2,%3};" \
        : "+f"(c[0]),"+f"(c[1]),"+f"(c[2]),"+f"(c[3]) \
        : "r"(A0),"r"(A1),"r"(A2),"r"(A3),"r"(B0),"r"(B1))
// 3-pass split mma: C += a.hi*b.hi + a.hi*b.lo + a.lo*b.hi
#define MMA3(c, a, b) do { \
    MMA(c, a[0].hi,a[1].hi,a[2].hi,a[3].hi, b[0].hi,b[1].hi); \
    MMA(c, a[0].hi,a[1].hi,a[2].hi,a[3].hi, b[0].lo,b[1].lo); \
    MMA(c, a[0].lo,a[1].lo,a[2].lo,a[3].lo, b[0].hi,b[1].hi); \
} while (0)

// ---------------------------------------------------------------------------
// Kernel 1: local block GEMM with fc-weight folding fused into the A loader.
// ---------------------------------------------------------------------------
__global__ __launch_bounds__(256) void lb_kernel(const float* __restrict__ q,
                                                 const float* __restrict__ k,
                                                 const float* __restrict__ fc_w,
                                                 const float* __restrict__ fc_b) {
    __shared__ float sA[64][65];
    __shared__ float sB[64][65];
    const int b  = blockIdx.z;
    const int i0 = blockIdx.y * 64;
    const int j0 = blockIdx.x * 64;
    const int tid = threadIdx.x;
    const int txn = tid & 15;
    const int tym = tid >> 4;

    float w[9];
    #pragma unroll
    for (int x = 0; x < 9; ++x) w[x] = __ldg(fc_w + x);

    const float* qb = q + (size_t)b * L * D;
    const float* kb = k + (size_t)b * L * D;

    float acc[4][4] = {};

    for (int k0 = 0; k0 < KD; k0 += 64) {
        #pragma unroll
        for (int it = 0; it < 4; ++it) {
            int lin = tid + it * 256;
            int r  = lin >> 4;
            int c4 = lin & 15;
            int kcol = k0 + c4 * 4;
            int c = kcol >> 7;
            int d = kcol & 127;
            const float* qr = qb + (size_t)(3 * (i0 + r)) * D + d;
            float4 q0 = *(const float4*)qr;
            float4 q1 = *(const float4*)(qr + D);
            float4 q2 = *(const float4*)(qr + 2 * D);
            float w0 = w[c], w1 = w[3 + c], w2 = w[6 + c];
            sA[r][c4 * 4 + 0] = w0 * q0.x + w1 * q1.x + w2 * q2.x;
            sA[r][c4 * 4 + 1] = w0 * q0.y + w1 * q1.y + w2 * q2.y;
            sA[r][c4 * 4 + 2] = w0 * q0.z + w1 * q1.z + w2 * q2.z;
            sA[r][c4 * 4 + 3] = w0 * q0.w + w1 * q1.w + w2 * q2.w;
            float4 bv = *(const float4*)(kb + (size_t)(j0 + r) * KD + kcol);
            sB[r][c4 * 4 + 0] = bv.x; sB[r][c4 * 4 + 1] = bv.y;
            sB[r][c4 * 4 + 2] = bv.z; sB[r][c4 * 4 + 3] = bv.w;
        }
        __syncthreads();
        #pragma unroll 8
        for (int kk = 0; kk < 64; ++kk) {
            float a[4], bb[4];
            #pragma unroll
            for (int i = 0; i < 4; ++i) a[i]  = sA[tym * 4 + i][kk];
            #pragma unroll
            for (int j = 0; j < 4; ++j) bb[j] = sB[txn + 16 * j][kk];
            #pragma unroll
            for (int i = 0; i < 4; ++i)
                #pragma unroll
                for (int j = 0; j < 4; ++j) acc[i][j] += a[i] * bb[j];
        }
        __syncthreads();
    }

    const float bias = 128.0f * fc_b[0];
    float* Lbp = g_Lb + (size_t)b * L3 * L3;
    #pragma unroll
    for (int i = 0; i < 4; ++i)
        #pragma unroll
        for (int j = 0; j < 4; ++j)
            Lbp[(size_t)(i0 + tym * 4 + i) * L3 + (j0 + txn + 16 * j)] = acc[i][j] + bias;
}

// ---------------------------------------------------------------------------
// Kernel 2: fused attention on tensor cores (tf32 mma, 3-pass hi/lo split).
// One CTA = (batch b, 32 query rows), 128 threads (4 warps), 3 CTAs/SM.
// Per 64-col chunk: S via mma -> e=exp((S+Lb)/T) -> attn + sE -> O += E@V via
// mma. Phase1: warp w owns n in [16w,16w+16). Phase2: warp w owns d in
// [32w,32w+32). Row sums cross warps -> sRS reduction at the end.
// SMEM floats: sQ 32x132 | sKV 64x136(max) | sE 32x68 | sRS 32x4 = 15,232
// ---------------------------------------------------------------------------
#define QS 132   // sQ row stride
#define KS 132   // sKV row stride when holding K ([n][k])
#define VS 136   // sKV row stride when holding V ([k][d])
#define ES 68    // sE row stride
#define SM_Q   0
#define SM_KV  (32 * QS)
#define SM_E   (32 * QS + 64 * VS)
#define SM_RS  (32 * QS + 64 * VS + 32 * ES)
#define SMEM_FLOATS (32 * QS + 64 * VS + 32 * ES + 32 * 4)

__global__ __launch_bounds__(128, 3) void fused_attn_kernel(
    const float* __restrict__ q, const float* __restrict__ k,
    const float* __restrict__ v, float* __restrict__ out,
    float* __restrict__ attn) {
    extern __shared__ float smem[];
    float* sQ  = smem + SM_Q;
    float* sKV = smem + SM_KV;
    float* sE  = smem + SM_E;
    float* sRS = smem + SM_RS;

    const int b   = blockIdx.y;
    const int m0  = blockIdx.x * 32;
    const int tid = threadIdx.x;
    const int tx  = tid & 31;
    const int wid = tid >> 5;       // 0..3
    const int gid = tx >> 2;        // 0..7
    const int tig = tx & 3;         // 0..3

    // ---- load q tile [m][d] into sQ (stride 132) ----
    #pragma unroll
    for (int it = 0; it < 8; ++it) {
        int lin = tid + it * 128;
        int m  = lin >> 5;
        int d4 = lin & 31;
        float4 qv = *(const float4*)(q + (size_t)((b * L + m0 + m) * D) + d4 * 4);
        *(float4*)(sQ + m * QS + d4 * 4) = qv;
    }

    const float* Lbp = g_Lb + (size_t)b * L3 * L3;
    int qi[4];
    #pragma unroll
    for (int r = 0; r < 4; ++r) qi[r] = (m0 + gid + 8 * r) / 3;

    float O[2][4][4] = {};     // [mt][dt][reg]
    float rsum[4] = {};

    for (int c = 0; c < 12; ++c) {
        // ---- load K chunk into sKV[n][k], stride 132 ----
        #pragma unroll
        for (int it = 0; it < 16; ++it) {
            int lin = tid + it * 128;
            int n  = lin >> 5;
            int d4 = lin & 31;
            float4 kv = *(const float4*)(k + (size_t)((b * L + c * 64 + n) * D) + d4 * 4);
            *(float4*)(sKV + n * KS + d4 * 4) = kv;
        }
        __syncthreads();

        // ---- S = Q @ K^T via tf32 mma (split) ----
        float C[2][2][4] = {};   // [mt][nt][reg]
        #pragma unroll 2
        for (int kt = 0; kt < 16; ++kt) {
            int kk = kt * 8;
            HL a[2][4];
            #pragma unroll
            for (int mt = 0; mt < 2; ++mt) {
                int r0 = (gid + 16 * mt) * QS + kk + tig;
                int r1 = (gid + 16 * mt + 8) * QS + kk + tig;
                a[mt][0] = split_tf32(sQ[r0]);
                a[mt][1] = split_tf32(sQ[r1]);
                a[mt][2] = split_tf32(sQ[r0 + 4]);
                a[mt][3] = split_tf32(sQ[r1 + 4]);
            }
            #pragma unroll
            for (int nt = 0; nt < 2; ++nt) {
                HL bf[2];
                int rb = (16 * wid + 8 * nt + gid) * KS + kk + tig;
                bf[0] = split_tf32(sKV[rb]);
                bf[1] = split_tf32(sKV[rb + 4]);
                MMA3(C[0][nt], a[0], bf);
                MMA3(C[1][nt], a[1], bf);
            }
        }

        // ---- epilogue: e = exp((S+Lb)/T); sE, attn, rsum ----
        #pragma unroll
        for (int nt = 0; nt < 2; ++nt) {
            int ncol = c * 64 + 16 * wid + 8 * nt + 2 * tig;
            int kj0 = ncol / 3, kj1 = (ncol + 1) / 3;
            #pragma unroll
            for (int mt = 0; mt < 2; ++mt)
                #pragma unroll
                for (int h = 0; h < 2; ++h) {
                    int rp = 2 * mt + h;
                    int m  = gid + 8 * rp;
                    const float* lbr = Lbp + (size_t)qi[rp] * L3;
                    float e0 = __expf((C[mt][nt][2 * h]     + __ldg(lbr + kj0)) * INV_T);
                    float e1 = __expf((C[mt][nt][2 * h + 1] + __ldg(lbr + kj1)) * INV_T);
                    rsum[rp] += e0 + e1;
                    float2 ee = make_float2(e0, e1);
                    *(float2*)(sE + m * ES + 16 * wid + 8 * nt + 2 * tig) = ee;
                    *(float2*)(attn + (size_t)(b * L + m0 + m) * L + ncol) = ee;
                }
        }
        __syncthreads();

        // ---- load V chunk into sKV[kv][d], stride 136 ----
        #pragma unroll
        for (int it = 0; it < 16; ++it) {
            int lin = tid + it * 128;
            int n  = lin >> 5;
            int d4 = lin & 31;
            float4 vv = *(const float4*)(v + (size_t)((b * L + c * 64 + n) * D) + d4 * 4);
            *(float4*)(sKV + n * VS + d4 * 4) = vv;
        }
        __syncthreads();

        // ---- O += E @ V via tf32 mma (split) ----
        #pragma unroll 1
        for (int kt = 0; kt < 8; ++kt) {
            int kk = kt * 8;
            HL a[2][4];
            #pragma unroll
            for (int mt = 0; mt < 2; ++mt) {
                int r0 = (gid + 16 * mt) * ES + kk + tig;
                int r1 = (gid + 16 * mt + 8) * ES + kk + tig;
                a[mt][0] = split_tf32(sE[r0]);
                a[mt][1] = split_tf32(sE[r1]);
                a[mt][2] = split_tf32(sE[r0 + 4]);
                a[mt][3] = split_tf32(sE[r1 + 4]);
            }
            #pragma unroll
            for (int dt = 0; dt < 4; ++dt) {
                HL bf[2];
                int cb = 32 * wid + 8 * dt + gid;
                bf[0] = split_tf32(sKV[(kk + tig) * VS + cb]);
                bf[1] = split_tf32(sKV[(kk + tig + 4) * VS + cb]);
                MMA3(O[0][dt], a[0], bf);
                MMA3(O[1][dt], a[1], bf);
            }
        }
        __syncthreads();
    }

    // ---- cross-warp row sums ----
    #pragma unroll
    for (int rp = 0; rp < 4; ++rp) {
        float s = rsum[rp];
        s += __shfl_xor_sync(0xffffffffu, s, 1);
        s += __shfl_xor_sync(0xffffffffu, s, 2);
        if (tig == 0) sRS[(gid + 8 * rp) * 4 + wid] = s;
    }
    __syncthreads();
    float inv[4];
    #pragma unroll
    for (int rp = 0; rp < 4; ++rp) {
        const float* p = sRS + (gid + 8 * rp) * 4;
        inv[rp] = 1.0f / (p[0] + p[1] + p[2] + p[3]);
    }

    // ---- normalize attn in place (just-written -> L2 hits) ----
    #pragma unroll
    for (int rp = 0; rp < 4; ++rp) {
        float* arow = attn + (size_t)(b * L + m0 + gid + 8 * rp) * L;
        float iv = inv[rp];
        #pragma unroll
        for (int t = 0; t < 12; ++t) {
            float4* p = (float4*)arow + wid * 48 + tig * 12 + t;
            float4 vv = *p;
            vv.x *= iv; vv.y *= iv; vv.z *= iv; vv.w *= iv;
            *p = vv;
        }
    }

    // ---- normalized output ----
    #pragma unroll
    for (int mt = 0; mt < 2; ++mt)
        #pragma unroll
        for (int dt = 0; dt < 4; ++dt)
            #pragma unroll
            for (int h = 0; h < 2; ++h) {
                int rp = 2 * mt + h;
                int m  = gid + 8 * rp;
                float iv = inv[rp];
                float2 o = make_float2(O[mt][dt][2 * h] * iv, O[mt][dt][2 * h + 1] * iv);
                *(float2*)(out + (size_t)(b * L + m0 + m) * D + 32 * wid + 8 * dt + 2 * tig) = o;
            }
}

// ---------------------------------------------------------------------------
extern "C" void kernel_launch(void* const* d_in, const int* in_sizes, int n_in,
                              void* d_out, int out_size) {
    const float* q    = (const float*)d_in[0];
    const float* k    = (const float*)d_in[1];
    const float* v    = (const float*)d_in[2];
    const float* fc_w = (const float*)d_in[3];
    const float* fc_b = (const float*)d_in[4];

    float* out  = (float*)d_out;
    float* attn = out + (size_t)NB * L * D;

    lb_kernel<<<dim3(4, 4, NB), 256>>>(q, k, fc_w, fc_b);

    const int smem_bytes = SMEM_FLOATS * sizeof(float);   // 60,928
    cudaFuncSetAttribute(fused_attn_kernel,
                         cudaFuncAttributeMaxDynamicSharedMemorySize, smem_bytes);
    fused_attn_kernel<<<dim3(24, NB), 128, smem_bytes>>>(q, k, v, out, attn);
}

// round 11
// speedup vs baseline: 1.2280x; 1.0649x over previous
#include <cuda_runtime.h>

#define NB 16
#define L 768
#define D 128
#define L3 256          // L / CLIP
#define KD 384          // CLIP * D
#define INV_T 0.08838834764831845f   // 1/sqrt(128)

__device__ float g_Lb[NB * L3 * L3 + 512];

// ---- tf32 helpers -------------------------------------------------------
__device__ __forceinline__ unsigned cvt_tf32(float v) {
    unsigned r; asm("cvt.rna.tf32.f32 %0, %1;" : "=r"(r) : "f"(v)); return r;
}
struct HL { unsigned hi, lo; };
__device__ __forceinline__ HL split_tf32(float v) {
    HL h; h.hi = cvt_tf32(v);
    h.lo = cvt_tf32(v - __uint_as_float(h.hi));
    return h;
}
#define MMA(c, A0,A1,A2,A3, B0,B1) \
    asm("mma.sync.aligned.m16n8k8.row.col.f32.tf32.tf32.f32 " \
        "{%0,%1,%2,%3},{%4,%5,%6,%7},{%8,%9},{%0,%1,%2,%3};" \
        : "+f"(c[0]),"+f"(c[1]),"+f"(c[2]),"+f"(c[3]) \
        : "r"(A0),"r"(A1),"r"(A2),"r"(A3),"r"(B0),"r"(B1))
// 3-pass split: C += ah*bh + ah*bl + al*bh   (a given as separate hi/lo regs)
#define MMA3S(c, ah, al, b0, b1) do { \
    MMA(c, ah[0],ah[1],ah[2],ah[3], b0.hi,b1.hi); \
    MMA(c, ah[0],ah[1],ah[2],ah[3], b0.lo,b1.lo); \
    MMA(c, al[0],al[1],al[2],al[3], b0.hi,b1.hi); \
} while (0)

// ---------------------------------------------------------------------------
// Kernel 1: local block GEMM with fc-weight folding fused into the A loader.
// ---------------------------------------------------------------------------
__global__ __launch_bounds__(256) void lb_kernel(const float* __restrict__ q,
                                                 const float* __restrict__ k,
                                                 const float* __restrict__ fc_w,
                                                 const float* __restrict__ fc_b) {
    __shared__ float sA[64][65];
    __shared__ float sB[64][65];
    const int b  = blockIdx.z;
    const int i0 = blockIdx.y * 64;
    const int j0 = blockIdx.x * 64;
    const int tid = threadIdx.x;
    const int txn = tid & 15;
    const int tym = tid >> 4;

    float w[9];
    #pragma unroll
    for (int x = 0; x < 9; ++x) w[x] = __ldg(fc_w + x);

    const float* qb = q + (size_t)b * L * D;
    const float* kb = k + (size_t)b * L * D;

    float acc[4][4] = {};

    for (int k0 = 0; k0 < KD; k0 += 64) {
        #pragma unroll
        for (int it = 0; it < 4; ++it) {
            int lin = tid + it * 256;
            int r  = lin >> 4;
            int c4 = lin & 15;
            int kcol = k0 + c4 * 4;
            int c = kcol >> 7;
            int d = kcol & 127;
            const float* qr = qb + (size_t)(3 * (i0 + r)) * D + d;
            float4 q0 = *(const float4*)qr;
            float4 q1 = *(const float4*)(qr + D);
            float4 q2 = *(const float4*)(qr + 2 * D);
            float w0 = w[c], w1 = w[3 + c], w2 = w[6 + c];
            sA[r][c4 * 4 + 0] = w0 * q0.x + w1 * q1.x + w2 * q2.x;
            sA[r][c4 * 4 + 1] = w0 * q0.y + w1 * q1.y + w2 * q2.y;
            sA[r][c4 * 4 + 2] = w0 * q0.z + w1 * q1.z + w2 * q2.z;
            sA[r][c4 * 4 + 3] = w0 * q0.w + w1 * q1.w + w2 * q2.w;
            float4 bv = *(const float4*)(kb + (size_t)(j0 + r) * KD + kcol);
            sB[r][c4 * 4 + 0] = bv.x; sB[r][c4 * 4 + 1] = bv.y;
            sB[r][c4 * 4 + 2] = bv.z; sB[r][c4 * 4 + 3] = bv.w;
        }
        __syncthreads();
        #pragma unroll 8
        for (int kk = 0; kk < 64; ++kk) {
            float a[4], bb[4];
            #pragma unroll
            for (int i = 0; i < 4; ++i) a[i]  = sA[tym * 4 + i][kk];
            #pragma unroll
            for (int j = 0; j < 4; ++j) bb[j] = sB[txn + 16 * j][kk];
            #pragma unroll
            for (int i = 0; i < 4; ++i)
                #pragma unroll
                for (int j = 0; j < 4; ++j) acc[i][j] += a[i] * bb[j];
        }
        __syncthreads();
    }

    const float bias = 128.0f * fc_b[0];
    float* Lbp = g_Lb + (size_t)b * L3 * L3;
    #pragma unroll
    for (int i = 0; i < 4; ++i)
        #pragma unroll
        for (int j = 0; j < 4; ++j)
            Lbp[(size_t)(i0 + tym * 4 + i) * L3 + (j0 + txn + 16 * j)] = acc[i][j] + bias;
}

// ---------------------------------------------------------------------------
// Kernel 2: fused attention on tensor cores, tf32 3-pass split with operand
// splits hoisted out of the hot loop:
//   - Q pre-split once into hi/lo SMEM planes
//   - E split at the epilogue (where it's produced) into hi/lo planes
//   - only K and V split in the consumers (non-redundant)
// One CTA = (b, 32 q-rows), 128 threads (4 warps), chunk = 32 cols, 24 chunks,
// 3 CTAs/SM. Phase1: warp w owns n in [8w,8w+8). Phase2: d in [32w,32w+32).
// SMEM floats: Qhi/Qlo 32x132 ea | KV 32x136 | Ehi/Elo 32x36 ea | RS 128
//            = 15,232 floats = 60,928 B -> 3 CTAs/SM.
// ---------------------------------------------------------------------------
#define QS 132
#define KS 132
#define VS 136
#define ES 36
#define SM_QH 0
#define SM_QL (32 * QS)
#define SM_KV (2 * 32 * QS)
#define SM_EH (2 * 32 * QS + 32 * VS)
#define SM_EL (2 * 32 * QS + 32 * VS + 32 * ES)
#define SM_RS (2 * 32 * QS + 32 * VS + 2 * 32 * ES)
#define SMEM_FLOATS (2 * 32 * QS + 32 * VS + 2 * 32 * ES + 128)

__global__ __launch_bounds__(128, 3) void fused_attn_kernel(
    const float* __restrict__ q, const float* __restrict__ k,
    const float* __restrict__ v, float* __restrict__ out,
    float* __restrict__ attn) {
    extern __shared__ float smem[];
    float* sQh = smem + SM_QH;
    float* sQl = smem + SM_QL;
    float* sKV = smem + SM_KV;
    float* sEh = smem + SM_EH;
    float* sEl = smem + SM_EL;
    float* sRS = smem + SM_RS;

    const int b   = blockIdx.y;
    const int m0  = blockIdx.x * 32;
    const int tid = threadIdx.x;
    const int tx  = tid & 31;
    const int wid = tid >> 5;       // 0..3
    const int gid = tx >> 2;        // 0..7
    const int tig = tx & 3;         // 0..3

    // ---- load q tile and pre-split into hi/lo planes ----
    #pragma unroll
    for (int it = 0; it < 8; ++it) {
        int lin = tid + it * 128;
        int m  = lin >> 5;
        int d4 = lin & 31;
        float4 qv = *(const float4*)(q + (size_t)((b * L + m0 + m) * D) + d4 * 4);
        HL hx = split_tf32(qv.x), hy = split_tf32(qv.y);
        HL hz = split_tf32(qv.z), hw = split_tf32(qv.w);
        *(float4*)(sQh + m * QS + d4 * 4) = make_float4(
            __uint_as_float(hx.hi), __uint_as_float(hy.hi),
            __uint_as_float(hz.hi), __uint_as_float(hw.hi));
        *(float4*)(sQl + m * QS + d4 * 4) = make_float4(
            __uint_as_float(hx.lo), __uint_as_float(hy.lo),
            __uint_as_float(hz.lo), __uint_as_float(hw.lo));
    }

    const float* Lbp = g_Lb + (size_t)b * L3 * L3;
    int qi[4];
    #pragma unroll
    for (int r = 0; r < 4; ++r) qi[r] = (m0 + gid + 8 * r) / 3;

    float O[2][4][4] = {};     // [mt][dt][reg]
    float rsum[4] = {};

    for (int c = 0; c < 24; ++c) {
        // ---- load K chunk [n=32][k=128], stride 132 ----
        #pragma unroll
        for (int it = 0; it < 8; ++it) {
            int lin = tid + it * 128;
            int n  = lin >> 5;
            int d4 = lin & 31;
            float4 kv = *(const float4*)(k + (size_t)((b * L + c * 32 + n) * D) + d4 * 4);
            *(float4*)(sKV + n * KS + d4 * 4) = kv;
        }
        __syncthreads();

        // ---- S = Q @ K^T (warp owns n in [8w,8w+8)) ----
        float C[2][4] = {};
        #pragma unroll 4
        for (int kt = 0; kt < 16; ++kt) {
            int kk = kt * 8;
            int rb = (8 * wid + gid) * KS + kk + tig;
            HL b0 = split_tf32(sKV[rb]);
            HL b1 = split_tf32(sKV[rb + 4]);
            unsigned ah[2][4], al[2][4];
            #pragma unroll
            for (int mt = 0; mt < 2; ++mt) {
                int r0 = (16 * mt + gid) * QS + kk + tig;
                int r1 = r0 + 8 * QS;
                ah[mt][0] = __float_as_uint(sQh[r0]);
                ah[mt][1] = __float_as_uint(sQh[r1]);
                ah[mt][2] = __float_as_uint(sQh[r0 + 4]);
                ah[mt][3] = __float_as_uint(sQh[r1 + 4]);
                al[mt][0] = __float_as_uint(sQl[r0]);
                al[mt][1] = __float_as_uint(sQl[r1]);
                al[mt][2] = __float_as_uint(sQl[r0 + 4]);
                al[mt][3] = __float_as_uint(sQl[r1 + 4]);
            }
            MMA3S(C[0], ah[0], al[0], b0, b1);
            MMA3S(C[1], ah[1], al[1], b0, b1);
        }

        // ---- epilogue: e = exp((S+Lb)/T); split e -> planes; attn; rsum ----
        {
            int ncol = c * 32 + 8 * wid + 2 * tig;
            int kj0 = ncol / 3, kj1 = (ncol + 1) / 3;
            #pragma unroll
            for (int mt = 0; mt < 2; ++mt)
                #pragma unroll
                for (int h = 0; h < 2; ++h) {
                    int rp = 2 * mt + h;
                    int m  = gid + 8 * rp;
                    const float* lbr = Lbp + (size_t)qi[rp] * L3;
                    float e0 = __expf((C[mt][2 * h]     + __ldg(lbr + kj0)) * INV_T);
                    float e1 = __expf((C[mt][2 * h + 1] + __ldg(lbr + kj1)) * INV_T);
                    rsum[rp] += e0 + e1;
                    HL s0 = split_tf32(e0), s1 = split_tf32(e1);
                    int eoff = m * ES + 8 * wid + 2 * tig;
                    *(float2*)(sEh + eoff) = make_float2(__uint_as_float(s0.hi),
                                                         __uint_as_float(s1.hi));
                    *(float2*)(sEl + eoff) = make_float2(__uint_as_float(s0.lo),
                                                         __uint_as_float(s1.lo));
                    *(float2*)(attn + (size_t)(b * L + m0 + m) * L + ncol) =
                        make_float2(e0, e1);
                }
        }
        __syncthreads();

        // ---- load V chunk [kv=32][d=128], stride 136 ----
        #pragma unroll
        for (int it = 0; it < 8; ++it) {
            int lin = tid + it * 128;
            int n  = lin >> 5;
            int d4 = lin & 31;
            float4 vv = *(const float4*)(v + (size_t)((b * L + c * 32 + n) * D) + d4 * 4);
            *(float4*)(sKV + n * VS + d4 * 4) = vv;
        }
        __syncthreads();

        // ---- O += E @ V (warp owns d in [32w,32w+32)) ----
        #pragma unroll
        for (int kt = 0; kt < 4; ++kt) {
            int kk = kt * 8;
            unsigned ah[2][4], al[2][4];
            #pragma unroll
            for (int mt = 0; mt < 2; ++mt) {
                int r0 = (16 * mt + gid) * ES + kk + tig;
                int r1 = r0 + 8 * ES;
                ah[mt][0] = __float_as_uint(sEh[r0]);
                ah[mt][1] = __float_as_uint(sEh[r1]);
                ah[mt][2] = __float_as_uint(sEh[r0 + 4]);
                ah[mt][3] = __float_as_uint(sEh[r1 + 4]);
                al[mt][0] = __float_as_uint(sEl[r0]);
                al[mt][1] = __float_as_uint(sEl[r1]);
                al[mt][2] = __float_as_uint(sEl[r0 + 4]);
                al[mt][3] = __float_as_uint(sEl[r1 + 4]);
            }
            #pragma unroll
            for (int dt = 0; dt < 4; ++dt) {
                int cb = 32 * wid + 8 * dt + gid;
                HL b0 = split_tf32(sKV[(kk + tig) * VS + cb]);
                HL b1 = split_tf32(sKV[(kk + tig + 4) * VS + cb]);
                MMA3S(O[0][dt], ah[0], al[0], b0, b1);
                MMA3S(O[1][dt], ah[1], al[1], b0, b1);
            }
        }
        __syncthreads();
    }

    // ---- cross-warp row sums ----
    #pragma unroll
    for (int rp = 0; rp < 4; ++rp) {
        float s = rsum[rp];
        s += __shfl_xor_sync(0xffffffffu, s, 1);
        s += __shfl_xor_sync(0xffffffffu, s, 2);
        if (tig == 0) sRS[(gid + 8 * rp) * 4 + wid] = s;
    }
    __syncthreads();
    float inv[4];
    #pragma unroll
    for (int rp = 0; rp < 4; ++rp) {
        const float* p = sRS + (gid + 8 * rp) * 4;
        inv[rp] = 1.0f / (p[0] + p[1] + p[2] + p[3]);
    }

    // ---- normalize attn in place (just-written -> L2 hits) ----
    #pragma unroll
    for (int rp = 0; rp < 4; ++rp) {
        float* arow = attn + (size_t)(b * L + m0 + gid + 8 * rp) * L;
        float iv = inv[rp];
        #pragma unroll
        for (int t = 0; t < 12; ++t) {
            float4* p = (float4*)arow + wid * 48 + tig * 12 + t;
            float4 vv = *p;
            vv.x *= iv; vv.y *= iv; vv.z *= iv; vv.w *= iv;
            *p = vv;
        }
    }

    // ---- normalized output ----
    #pragma unroll
    for (int mt = 0; mt < 2; ++mt)
        #pragma unroll
        for (int dt = 0; dt < 4; ++dt)
            #pragma unroll
            for (int h = 0; h < 2; ++h) {
                int rp = 2 * mt + h;
                int m  = gid + 8 * rp;
                float iv = inv[rp];
                float2 o = make_float2(O[mt][dt][2 * h] * iv, O[mt][dt][2 * h + 1] * iv);
                *(float2*)(out + (size_t)(b * L + m0 + m) * D + 32 * wid + 8 * dt + 2 * tig) = o;
            }
}

// ---------------------------------------------------------------------------
extern "C" void kernel_launch(void* const* d_in, const int* in_sizes, int n_in,
                              void* d_out, int out_size) {
    const float* q    = (const float*)d_in[0];
    const float* k    = (const float*)d_in[1];
    const float* v    = (const float*)d_in[2];
    const float* fc_w = (const float*)d_in[3];
    const float* fc_b = (const float*)d_in[4];

    float* out  = (float*)d_out;
    float* attn = out + (size_t)NB * L * D;

    lb_kernel<<<dim3(4, 4, NB), 256>>>(q, k, fc_w, fc_b);

    const int smem_bytes = SMEM_FLOATS * sizeof(float);   // 60,928
    cudaFuncSetAttribute(fused_attn_kernel,
                         cudaFuncAttributeMaxDynamicSharedMemorySize, smem_bytes);
    fused_attn_kernel<<<dim3(24, NB), 128, smem_bytes>>>(q, k, v, out, attn);
}

// round 13
// speedup vs baseline: 1.6567x; 1.3491x over previous
#include <cuda_runtime.h>
#include <cuda_bf16.h>

#define NB 16
#define L 768
#define D 128
#define L3 256          // L / CLIP
#define KD 384          // CLIP * D
#define INV_T 0.08838834764831845f   // 1/sqrt(128)

__device__ float g_Lb[NB * L3 * L3 + 512];

typedef unsigned int u32;

// ---- bf16 split helpers --------------------------------------------------
__device__ __forceinline__ void split2(float x, float y, u32& hi, u32& lo) {
    __nv_bfloat16 hx = __float2bfloat16(x);
    __nv_bfloat16 hy = __float2bfloat16(y);
    __nv_bfloat16 lx = __float2bfloat16(x - __bfloat162float(hx));
    __nv_bfloat16 ly = __float2bfloat16(y - __bfloat162float(hy));
    __nv_bfloat162 h2 = __nv_bfloat162(hx, hy);
    __nv_bfloat162 l2 = __nv_bfloat162(lx, ly);
    hi = *(u32*)&h2;
    lo = *(u32*)&l2;
}

// ---- fast exp on fma/alu pipes (rel err ~3e-6) ---------------------------
__device__ __forceinline__ float fast_exp(float x) {
    float t = x * 1.4426950408889634f;
    float r = rintf(t);
    float f = t - r;
    float p = 1.3333558146428443e-3f;
    p = fmaf(p, f, 9.6181291076284772e-3f);
    p = fmaf(p, f, 5.5504108664821580e-2f);
    p = fmaf(p, f, 2.4022650695910072e-1f);
    p = fmaf(p, f, 6.9314718055994531e-1f);
    p = fmaf(p, f, 1.0f);
    return __int_as_float(__float_as_int(p) + ((int)r << 23));
}

// ---- ldmatrix / mma ------------------------------------------------------
#define LDSM4(R0,R1,R2,R3,ADDR) \
    asm volatile("ldmatrix.sync.aligned.m8n8.x4.shared.b16 {%0,%1,%2,%3},[%4];" \
        : "=r"(R0),"=r"(R1),"=r"(R2),"=r"(R3) : "r"(ADDR))
#define LDSM2(R0,R1,ADDR) \
    asm volatile("ldmatrix.sync.aligned.m8n8.x2.shared.b16 {%0,%1},[%2];" \
        : "=r"(R0),"=r"(R1) : "r"(ADDR))
#define LDSM2T(R0,R1,ADDR) \
    asm volatile("ldmatrix.sync.aligned.m8n8.x2.trans.shared.b16 {%0,%1},[%2];" \
        : "=r"(R0),"=r"(R1) : "r"(ADDR))
#define MMAB(c, a, b0, b1) \
    asm("mma.sync.aligned.m16n8k16.row.col.f32.bf16.bf16.f32 " \
        "{%0,%1,%2,%3},{%4,%5,%6,%7},{%8,%9},{%0,%1,%2,%3};" \
        : "+f"(c[0]),"+f"(c[1]),"+f"(c[2]),"+f"(c[3]) \
        : "r"(a[0]),"r"(a[1]),"r"(a[2]),"r"(a[3]),"r"(b0),"r"(b1))

// ---------------------------------------------------------------------------
// Kernel 1: local block GEMM with fc-weight folding fused into the A loader.
// ---------------------------------------------------------------------------
__global__ __launch_bounds__(256) void lb_kernel(const float* __restrict__ q,
                                                 const float* __restrict__ k,
                                                 const float* __restrict__ fc_w,
                                                 const float* __restrict__ fc_b) {
    __shared__ float sA[64][65];
    __shared__ float sB[64][65];
    const int b  = blockIdx.z;
    const int i0 = blockIdx.y * 64;
    const int j0 = blockIdx.x * 64;
    const int tid = threadIdx.x;
    const int txn = tid & 15;
    const int tym = tid >> 4;

    float w[9];
    #pragma unroll
    for (int x = 0; x < 9; ++x) w[x] = __ldg(fc_w + x);

    const float* qb = q + (size_t)b * L * D;
    const float* kb = k + (size_t)b * L * D;

    float acc[4][4] = {};

    for (int k0 = 0; k0 < KD; k0 += 64) {
        #pragma unroll
        for (int it = 0; it < 4; ++it) {
            int lin = tid + it * 256;
            int r  = lin >> 4;
            int c4 = lin & 15;
            int kcol = k0 + c4 * 4;
            int c = kcol >> 7;
            int d = kcol & 127;
            const float* qr = qb + (size_t)(3 * (i0 + r)) * D + d;
            float4 q0 = *(const float4*)qr;
            float4 q1 = *(const float4*)(qr + D);
            float4 q2 = *(const float4*)(qr + 2 * D);
            float w0 = w[c], w1 = w[3 + c], w2 = w[6 + c];
            sA[r][c4 * 4 + 0] = w0 * q0.x + w1 * q1.x + w2 * q2.x;
            sA[r][c4 * 4 + 1] = w0 * q0.y + w1 * q1.y + w2 * q2.y;
            sA[r][c4 * 4 + 2] = w0 * q0.z + w1 * q1.z + w2 * q2.z;
            sA[r][c4 * 4 + 3] = w0 * q0.w + w1 * q1.w + w2 * q2.w;
            float4 bv = *(const float4*)(kb + (size_t)(j0 + r) * KD + kcol);
            sB[r][c4 * 4 + 0] = bv.x; sB[r][c4 * 4 + 1] = bv.y;
            sB[r][c4 * 4 + 2] = bv.z; sB[r][c4 * 4 + 3] = bv.w;
        }
        __syncthreads();
        #pragma unroll 8
        for (int kk = 0; kk < 64; ++kk) {
            float a[4], bb[4];
            #pragma unroll
            for (int i = 0; i < 4; ++i) a[i]  = sA[tym * 4 + i][kk];
            #pragma unroll
            for (int j = 0; j < 4; ++j) bb[j] = sB[txn + 16 * j][kk];
            #pragma unroll
            for (int i = 0; i < 4; ++i)
                #pragma unroll
                for (int j = 0; j < 4; ++j) acc[i][j] += a[i] * bb[j];
        }
        __syncthreads();
    }

    const float bias = 128.0f * fc_b[0];
    float* Lbp = g_Lb + (size_t)b * L3 * L3;
    #pragma unroll
    for (int i = 0; i < 4; ++i)
        #pragma unroll
        for (int j = 0; j < 4; ++j)
            Lbp[(size_t)(i0 + tym * 4 + i) * L3 + (j0 + txn + 16 * j)] = acc[i][j] + bias;
}

// ---------------------------------------------------------------------------
// Kernel 2: fused attention, bf16 double-split tensor cores + ldmatrix.
// One CTA = (b, 32 q-rows), 128 threads (4 warps), chunk = 32, 24 chunks,
// 4 CTAs/SM. 3 mma passes (hh, hl, lh) per operand pair.
// Phase1: warp w owns n in [8w,8w+8). Phase2: warp w owns d in [32w,32w+32).
// SMEM bytes: Qh/Ql 32x136 bf16 (8704 ea) | KVh/KVl 32x136 bf16 (8704 ea) |
//             Eh/El 32x40 bf16 (2560 ea) | RS 512  = 40,448 B.
// ---------------------------------------------------------------------------
#define OFF_QH 0
#define OFF_QL 8704
#define OFF_KH 17408
#define OFF_KL 26112
#define OFF_EH 34816
#define OFF_EL 37376
#define OFF_RS 39936
#define SMEM_BYTES 40448

__global__ __launch_bounds__(128, 4) void fused_attn_kernel(
    const float* __restrict__ q, const float* __restrict__ k,
    const float* __restrict__ v, float* __restrict__ out,
    float* __restrict__ attn) {
    extern __shared__ __align__(16) char smem[];
    __nv_bfloat16* sQh = (__nv_bfloat16*)(smem + OFF_QH);
    __nv_bfloat16* sQl = (__nv_bfloat16*)(smem + OFF_QL);
    __nv_bfloat16* sKh = (__nv_bfloat16*)(smem + OFF_KH);
    __nv_bfloat16* sKl = (__nv_bfloat16*)(smem + OFF_KL);
    __nv_bfloat16* sEh = (__nv_bfloat16*)(smem + OFF_EH);
    __nv_bfloat16* sEl = (__nv_bfloat16*)(smem + OFF_EL);
    float* sRS = (float*)(smem + OFF_RS);
    const u32 sbase = (u32)__cvta_generic_to_shared(smem);

    const int b    = blockIdx.y;
    const int m0   = blockIdx.x * 32;
    const int tid  = threadIdx.x;
    const int lane = tid & 31;
    const int wid  = tid >> 5;
    const int gid  = lane >> 2;
    const int tig  = lane & 3;

    // ---- load q tile, split into bf16 hi/lo planes ----
    #pragma unroll
    for (int it = 0; it < 8; ++it) {
        int lin = tid + it * 128;
        int m  = lin >> 5;
        int d4 = lin & 31;
        float4 qv = *(const float4*)(q + (size_t)((b * L + m0 + m) * D) + d4 * 4);
        u32 h0, l0, h1, l1;
        split2(qv.x, qv.y, h0, l0);
        split2(qv.z, qv.w, h1, l1);
        *(uint2*)(sQh + m * 136 + d4 * 4) = make_uint2(h0, h1);
        *(uint2*)(sQl + m * 136 + d4 * 4) = make_uint2(l0, l1);
    }

    const float* Lbp = g_Lb + (size_t)b * L3 * L3;
    int qi[4];
    #pragma unroll
    for (int r = 0; r < 4; ++r) qi[r] = (m0 + gid + 8 * r) / 3;

    // ldmatrix lane address offsets (bytes)
    const u32 aQ = sbase + OFF_QH + (lane & 15) * 272 + ((lane >> 4) << 4);
    const u32 aK = sbase + OFF_KH + (8 * wid + (lane & 7)) * 272 + ((lane & 8) ? 16 : 0);
    const u32 aE = sbase + OFF_EH + (lane & 15) * 80 + ((lane >> 4) << 4);
    const u32 aV = sbase + OFF_KH + (lane & 15) * 272 + 64 * wid;

    float O[2][4][4] = {};
    float rsum[4] = {};

    for (int c = 0; c < 24; ++c) {
        // ---- load K chunk, split into hi/lo ----
        #pragma unroll
        for (int it = 0; it < 8; ++it) {
            int lin = tid + it * 128;
            int n  = lin >> 5;
            int d4 = lin & 31;
            float4 kv = *(const float4*)(k + (size_t)((b * L + c * 32 + n) * D) + d4 * 4);
            u32 h0, l0, h1, l1;
            split2(kv.x, kv.y, h0, l0);
            split2(kv.z, kv.w, h1, l1);
            *(uint2*)(sKh + n * 136 + d4 * 4) = make_uint2(h0, h1);
            *(uint2*)(sKl + n * 136 + d4 * 4) = make_uint2(l0, l1);
        }
        __syncthreads();

        // ---- S = Q @ K^T, 3-pass bf16 split ----
        float C[2][4] = {};
        #pragma unroll
        for (int kt = 0; kt < 8; ++kt) {
            u32 bh[2], bl[2];
            LDSM2(bh[0], bh[1], aK + kt * 32);
            LDSM2(bl[0], bl[1], aK + 8704 + kt * 32);
            #pragma unroll
            for (int mt = 0; mt < 2; ++mt) {
                u32 ah[4], al[4];
                LDSM4(ah[0], ah[1], ah[2], ah[3], aQ + mt * 4352 + kt * 32);
                LDSM4(al[0], al[1], al[2], al[3], aQ + 8704 + mt * 4352 + kt * 32);
                MMAB(C[mt], ah, bh[0], bh[1]);
                MMAB(C[mt], ah, bl[0], bl[1]);
                MMAB(C[mt], al, bh[0], bh[1]);
            }
        }

        // ---- epilogue: e = exp((S+Lb)/T); split e; attn; rsum ----
        {
            int ncol = c * 32 + 8 * wid + 2 * tig;
            int kj0 = ncol / 3, kj1 = (ncol + 1) / 3;
            #pragma unroll
            for (int mt = 0; mt < 2; ++mt)
                #pragma unroll
                for (int h = 0; h < 2; ++h) {
                    int rp = 2 * mt + h;
                    int m  = gid + 8 * rp;
                    const float* lbr = Lbp + (size_t)qi[rp] * L3;
                    float e0 = fast_exp((C[mt][2 * h]     + __ldg(lbr + kj0)) * INV_T);
                    float e1 = fast_exp((C[mt][2 * h + 1] + __ldg(lbr + kj1)) * INV_T);
                    rsum[rp] += e0 + e1;
                    u32 ehi, elo;
                    split2(e0, e1, ehi, elo);
                    *(u32*)(sEh + m * 40 + 8 * wid + 2 * tig) = ehi;
                    *(u32*)(sEl + m * 40 + 8 * wid + 2 * tig) = elo;
                    *(float2*)(attn + (size_t)(b * L + m0 + m) * L + ncol) =
                        make_float2(e0, e1);
                }
        }
        __syncthreads();

        // ---- load V chunk (reuse K planes), split into hi/lo ----
        #pragma unroll
        for (int it = 0; it < 8; ++it) {
            int lin = tid + it * 128;
            int n  = lin >> 5;
            int d4 = lin & 31;
            float4 vv = *(const float4*)(v + (size_t)((b * L + c * 32 + n) * D) + d4 * 4);
            u32 h0, l0, h1, l1;
            split2(vv.x, vv.y, h0, l0);
            split2(vv.z, vv.w, h1, l1);
            *(uint2*)(sKh + n * 136 + d4 * 4) = make_uint2(h0, h1);
            *(uint2*)(sKl + n * 136 + d4 * 4) = make_uint2(l0, l1);
        }
        __syncthreads();

        // ---- O += E @ V, 3-pass bf16 split ----
        #pragma unroll
        for (int kt2 = 0; kt2 < 2; ++kt2) {
            u32 ah0[4], al0[4], ah1[4], al1[4];
            LDSM4(ah0[0], ah0[1], ah0[2], ah0[3], aE + kt2 * 32);
            LDSM4(al0[0], al0[1], al0[2], al0[3], aE + 2560 + kt2 * 32);
            LDSM4(ah1[0], ah1[1], ah1[2], ah1[3], aE + 1280 + kt2 * 32);
            LDSM4(al1[0], al1[1], al1[2], al1[3], aE + 2560 + 1280 + kt2 * 32);
            #pragma unroll
            for (int dt = 0; dt < 4; ++dt) {
                u32 bh[2], bl[2];
                LDSM2T(bh[0], bh[1], aV + kt2 * 4352 + dt * 16);
                LDSM2T(bl[0], bl[1], aV + 8704 + kt2 * 4352 + dt * 16);
                MMAB(O[0][dt], ah0, bh[0], bh[1]);
                MMAB(O[0][dt], ah0, bl[0], bl[1]);
                MMAB(O[0][dt], al0, bh[0], bh[1]);
                MMAB(O[1][dt], ah1, bh[0], bh[1]);
                MMAB(O[1][dt], ah1, bl[0], bl[1]);
                MMAB(O[1][dt], al1, bh[0], bh[1]);
            }
        }
        __syncthreads();
    }

    // ---- cross-warp row sums ----
    #pragma unroll
    for (int rp = 0; rp < 4; ++rp) {
        float s = rsum[rp];
        s += __shfl_xor_sync(0xffffffffu, s, 1);
        s += __shfl_xor_sync(0xffffffffu, s, 2);
        if (tig == 0) sRS[(gid + 8 * rp) * 4 + wid] = s;
    }
    __syncthreads();
    float inv[4];
    #pragma unroll
    for (int rp = 0; rp < 4; ++rp) {
        const float* p = sRS + (gid + 8 * rp) * 4;
        inv[rp] = 1.0f / (p[0] + p[1] + p[2] + p[3]);
    }

    // ---- normalize attn in place (just-written -> L2 hits) ----
    #pragma unroll
    for (int rp = 0; rp < 4; ++rp) {
        float* arow = attn + (size_t)(b * L + m0 + gid + 8 * rp) * L;
        float iv = inv[rp];
        #pragma unroll
        for (int t = 0; t < 12; ++t) {
            float4* p = (float4*)arow + wid * 48 + tig * 12 + t;
            float4 vv = *p;
            vv.x *= iv; vv.y *= iv; vv.z *= iv; vv.w *= iv;
            *p = vv;
        }
    }

    // ---- normalized output ----
    #pragma unroll
    for (int mt = 0; mt < 2; ++mt)
        #pragma unroll
        for (int dt = 0; dt < 4; ++dt)
            #pragma unroll
            for (int h = 0; h < 2; ++h) {
                int rp = 2 * mt + h;
                int m  = gid + 8 * rp;
                float iv = inv[rp];
                float2 o = make_float2(O[mt][dt][2 * h] * iv, O[mt][dt][2 * h + 1] * iv);
                *(float2*)(out + (size_t)(b * L + m0 + m) * D + 32 * wid + 8 * dt + 2 * tig) = o;
            }
}

// ---------------------------------------------------------------------------
extern "C" void kernel_launch(void* const* d_in, const int* in_sizes, int n_in,
                              void* d_out, int out_size) {
    const float* q    = (const float*)d_in[0];
    const float* k    = (const float*)d_in[1];
    const float* v    = (const float*)d_in[2];
    const float* fc_w = (const float*)d_in[3];
    const float* fc_b = (const float*)d_in[4];

    float* out  = (float*)d_out;
    float* attn = out + (size_t)NB * L * D;

    lb_kernel<<<dim3(4, 4, NB), 256>>>(q, k, fc_w, fc_b);

    cudaFuncSetAttribute(fused_attn_kernel,
                         cudaFuncAttributeMaxDynamicSharedMemorySize, SMEM_BYTES);
    fused_attn_kernel<<<dim3(24, NB), 128, SMEM_BYTES>>>(q, k, v, out, attn);
}

// round 15
// speedup vs baseline: 1.7120x; 1.0334x over previous
#include <cuda_runtime.h>
#include <cuda_bf16.h>

#define NB 16
#define L 768
#define D 128
#define L3 256          // L / CLIP
#define KD 384          // CLIP * D
#define INV_T 0.08838834764831845f   // 1/sqrt(128)

__device__ float g_Lb[NB * L3 * L3 + 512];

typedef unsigned int u32;

// ---- bf16 split helpers --------------------------------------------------
__device__ __forceinline__ void split2(float x, float y, u32& hi, u32& lo) {
    __nv_bfloat16 hx = __float2bfloat16(x);
    __nv_bfloat16 hy = __float2bfloat16(y);
    __nv_bfloat16 lx = __float2bfloat16(x - __bfloat162float(hx));
    __nv_bfloat16 ly = __float2bfloat16(y - __bfloat162float(hy));
    __nv_bfloat162 h2 = __nv_bfloat162(hx, hy);
    __nv_bfloat162 l2 = __nv_bfloat162(lx, ly);
    hi = *(u32*)&h2;
    lo = *(u32*)&l2;
}

// ---- fast exp on fma/alu pipes (rel err ~3e-6) ---------------------------
__device__ __forceinline__ float fast_exp(float x) {
    float t = x * 1.4426950408889634f;
    float r = rintf(t);
    float f = t - r;
    float p = 1.3333558146428443e-3f;
    p = fmaf(p, f, 9.6181291076284772e-3f);
    p = fmaf(p, f, 5.5504108664821580e-2f);
    p = fmaf(p, f, 2.4022650695910072e-1f);
    p = fmaf(p, f, 6.9314718055994531e-1f);
    p = fmaf(p, f, 1.0f);
    return __int_as_float(__float_as_int(p) + ((int)r << 23));
}

// ---- ldmatrix / mma ------------------------------------------------------
#define LDSM4(R0,R1,R2,R3,ADDR) \
    asm volatile("ldmatrix.sync.aligned.m8n8.x4.shared.b16 {%0,%1,%2,%3},[%4];" \
        : "=r"(R0),"=r"(R1),"=r"(R2),"=r"(R3) : "r"(ADDR))
#define LDSM2(R0,R1,ADDR) \
    asm volatile("ldmatrix.sync.aligned.m8n8.x2.shared.b16 {%0,%1},[%2];" \
        : "=r"(R0),"=r"(R1) : "r"(ADDR))
#define LDSM2T(R0,R1,ADDR) \
    asm volatile("ldmatrix.sync.aligned.m8n8.x2.trans.shared.b16 {%0,%1},[%2];" \
        : "=r"(R0),"=r"(R1) : "r"(ADDR))
#define MMAB(c, a, b0, b1) \
    asm("mma.sync.aligned.m16n8k16.row.col.f32.bf16.bf16.f32 " \
        "{%0,%1,%2,%3},{%4,%5,%6,%7},{%8,%9},{%0,%1,%2,%3};" \
        : "+f"(c[0]),"+f"(c[1]),"+f"(c[2]),"+f"(c[3]) \
        : "r"(a[0]),"r"(a[1]),"r"(a[2]),"r"(a[3]),"r"(b0),"r"(b1))

// ---------------------------------------------------------------------------
// Kernel 1: local block GEMM with fc-weight folding fused into the A loader.
// ---------------------------------------------------------------------------
__global__ __launch_bounds__(256) void lb_kernel(const float* __restrict__ q,
                                                 const float* __restrict__ k,
                                                 const float* __restrict__ fc_w,
                                                 const float* __restrict__ fc_b) {
    __shared__ float sA[64][65];
    __shared__ float sB[64][65];
    const int b  = blockIdx.z;
    const int i0 = blockIdx.y * 64;
    const int j0 = blockIdx.x * 64;
    const int tid = threadIdx.x;
    const int txn = tid & 15;
    const int tym = tid >> 4;

    float w[9];
    #pragma unroll
    for (int x = 0; x < 9; ++x) w[x] = __ldg(fc_w + x);

    const float* qb = q + (size_t)b * L * D;
    const float* kb = k + (size_t)b * L * D;

    float acc[4][4] = {};

    for (int k0 = 0; k0 < KD; k0 += 64) {
        #pragma unroll
        for (int it = 0; it < 4; ++it) {
            int lin = tid + it * 256;
            int r  = lin >> 4;
            int c4 = lin & 15;
            int kcol = k0 + c4 * 4;
            int c = kcol >> 7;
            int d = kcol & 127;
            const float* qr = qb + (size_t)(3 * (i0 + r)) * D + d;
            float4 q0 = *(const float4*)qr;
            float4 q1 = *(const float4*)(qr + D);
            float4 q2 = *(const float4*)(qr + 2 * D);
            float w0 = w[c], w1 = w[3 + c], w2 = w[6 + c];
            sA[r][c4 * 4 + 0] = w0 * q0.x + w1 * q1.x + w2 * q2.x;
            sA[r][c4 * 4 + 1] = w0 * q0.y + w1 * q1.y + w2 * q2.y;
            sA[r][c4 * 4 + 2] = w0 * q0.z + w1 * q1.z + w2 * q2.z;
            sA[r][c4 * 4 + 3] = w0 * q0.w + w1 * q1.w + w2 * q2.w;
            float4 bv = *(const float4*)(kb + (size_t)(j0 + r) * KD + kcol);
            sB[r][c4 * 4 + 0] = bv.x; sB[r][c4 * 4 + 1] = bv.y;
            sB[r][c4 * 4 + 2] = bv.z; sB[r][c4 * 4 + 3] = bv.w;
        }
        __syncthreads();
        #pragma unroll 8
        for (int kk = 0; kk < 64; ++kk) {
            float a[4], bb[4];
            #pragma unroll
            for (int i = 0; i < 4; ++i) a[i]  = sA[tym * 4 + i][kk];
            #pragma unroll
            for (int j = 0; j < 4; ++j) bb[j] = sB[txn + 16 * j][kk];
            #pragma unroll
            for (int i = 0; i < 4; ++i)
                #pragma unroll
                for (int j = 0; j < 4; ++j) acc[i][j] += a[i] * bb[j];
        }
        __syncthreads();
    }

    const float bias = 128.0f * fc_b[0];
    float* Lbp = g_Lb + (size_t)b * L3 * L3;
    #pragma unroll
    for (int i = 0; i < 4; ++i)
        #pragma unroll
        for (int j = 0; j < 4; ++j)
            Lbp[(size_t)(i0 + tym * 4 + i) * L3 + (j0 + txn + 16 * j)] = acc[i][j] + bias;
}

// ---------------------------------------------------------------------------
// Kernel 2: fused attention, bf16 double-split + ldmatrix, 8-warp CTAs.
// One CTA = (b, 32 q-rows), 256 threads (8 warps), chunk = 64, 12 chunks,
// 3 CTAs/SM (24 warps/SM). 3 mma passes (hh, hl, lh) per operand pair.
// Phase1: warp w owns n in [8w,8w+8). Phase2: warp w owns d in [16w,16w+16).
// SMEM bytes: Qh/Ql 32x136 (8704 ea) | KVh/KVl 64x136 (17408 ea) |
//             Eh/El 32x72 (4608 ea) | RS 1024  = 62,464 B.
// ---------------------------------------------------------------------------
#define OFF_QH 0
#define OFF_QL 8704
#define OFF_KH 17408
#define OFF_KL 34816
#define OFF_EH 52224
#define OFF_EL 56832
#define OFF_RS 61440
#define SMEM_BYTES 62464

__global__ __launch_bounds__(256, 3) void fused_attn_kernel(
    const float* __restrict__ q, const float* __restrict__ k,
    const float* __restrict__ v, float* __restrict__ out,
    float* __restrict__ attn) {
    extern __shared__ __align__(16) char smem[];
    __nv_bfloat16* sQh = (__nv_bfloat16*)(smem + OFF_QH);
    __nv_bfloat16* sQl = (__nv_bfloat16*)(smem + OFF_QL);
    __nv_bfloat16* sKh = (__nv_bfloat16*)(smem + OFF_KH);
    __nv_bfloat16* sKl = (__nv_bfloat16*)(smem + OFF_KL);
    __nv_bfloat16* sEh = (__nv_bfloat16*)(smem + OFF_EH);
    __nv_bfloat16* sEl = (__nv_bfloat16*)(smem + OFF_EL);
    float* sRS = (float*)(smem + OFF_RS);
    const u32 sbase = (u32)__cvta_generic_to_shared(smem);

    const int b    = blockIdx.y;
    const int m0   = blockIdx.x * 32;
    const int tid  = threadIdx.x;
    const int lane = tid & 31;
    const int wid  = tid >> 5;      // 0..7
    const int gid  = lane >> 2;
    const int tig  = lane & 3;

    // ---- load q tile, split into bf16 hi/lo planes ----
    #pragma unroll
    for (int it = 0; it < 4; ++it) {
        int lin = tid + it * 256;
        int m  = lin >> 5;
        int d4 = lin & 31;
        float4 qv = *(const float4*)(q + (size_t)((b * L + m0 + m) * D) + d4 * 4);
        u32 h0, l0, h1, l1;
        split2(qv.x, qv.y, h0, l0);
        split2(qv.z, qv.w, h1, l1);
        *(uint2*)(sQh + m * 136 + d4 * 4) = make_uint2(h0, h1);
        *(uint2*)(sQl + m * 136 + d4 * 4) = make_uint2(l0, l1);
    }

    const float* Lbp = g_Lb + (size_t)b * L3 * L3;
    int qi[4];
    #pragma unroll
    for (int r = 0; r < 4; ++r) qi[r] = (m0 + gid + 8 * r) / 3;

    // ldmatrix lane base addresses (bytes)
    const u32 aQ = sbase + OFF_QH + (lane & 15) * 272 + ((lane >> 4) << 4);
    const u32 aK = sbase + OFF_KH + (8 * wid + (lane & 7)) * 272 + ((lane & 8) ? 16 : 0);
    const u32 aE = sbase + OFF_EH + (lane & 15) * 144 + ((lane >> 4) << 4);
    const u32 aV = sbase + OFF_KH + (lane & 15) * 272 + 32 * wid;

    float O[2][2][4] = {};    // [mt][dt][reg]
    float rsum[4] = {};

    for (int c = 0; c < 12; ++c) {
        // ---- load K chunk (64 rows), split into hi/lo ----
        #pragma unroll
        for (int it = 0; it < 8; ++it) {
            int lin = tid + it * 256;
            int n  = lin >> 5;
            int d4 = lin & 31;
            float4 kv = *(const float4*)(k + (size_t)((b * L + c * 64 + n) * D) + d4 * 4);
            u32 h0, l0, h1, l1;
            split2(kv.x, kv.y, h0, l0);
            split2(kv.z, kv.w, h1, l1);
            *(uint2*)(sKh + n * 136 + d4 * 4) = make_uint2(h0, h1);
            *(uint2*)(sKl + n * 136 + d4 * 4) = make_uint2(l0, l1);
        }
        __syncthreads();

        // ---- S = Q @ K^T, 3-pass bf16 split (warp w: n in [8w,8w+8)) ----
        float C[2][4] = {};
        #pragma unroll
        for (int kt = 0; kt < 8; ++kt) {
            u32 bh[2], bl[2];
            LDSM2(bh[0], bh[1], aK + kt * 32);
            LDSM2(bl[0], bl[1], aK + 17408 + kt * 32);
            #pragma unroll
            for (int mt = 0; mt < 2; ++mt) {
                u32 ah[4], al[4];
                LDSM4(ah[0], ah[1], ah[2], ah[3], aQ + mt * 4352 + kt * 32);
                LDSM4(al[0], al[1], al[2], al[3], aQ + 8704 + mt * 4352 + kt * 32);
                MMAB(C[mt], ah, bh[0], bh[1]);
                MMAB(C[mt], ah, bl[0], bl[1]);
                MMAB(C[mt], al, bh[0], bh[1]);
            }
        }

        // ---- epilogue: e = exp((S+Lb)/T); split e; attn; rsum ----
        {
            int ncol = c * 64 + 8 * wid + 2 * tig;
            int kj0 = ncol / 3, kj1 = (ncol + 1) / 3;
            #pragma unroll
            for (int mt = 0; mt < 2; ++mt)
                #pragma unroll
                for (int h = 0; h < 2; ++h) {
                    int rp = 2 * mt + h;
                    int m  = gid + 8 * rp;
                    const float* lbr = Lbp + (size_t)qi[rp] * L3;
                    float e0 = fast_exp((C[mt][2 * h]     + __ldg(lbr + kj0)) * INV_T);
                    float e1 = fast_exp((C[mt][2 * h + 1] + __ldg(lbr + kj1)) * INV_T);
                    rsum[rp] += e0 + e1;
                    u32 ehi, elo;
                    split2(e0, e1, ehi, elo);
                    *(u32*)(sEh + m * 72 + 8 * wid + 2 * tig) = ehi;
                    *(u32*)(sEl + m * 72 + 8 * wid + 2 * tig) = elo;
                    *(float2*)(attn + (size_t)(b * L + m0 + m) * L + ncol) =
                        make_float2(e0, e1);
                }
        }
        __syncthreads();

        // ---- load V chunk (reuse K planes), split into hi/lo ----
        #pragma unroll
        for (int it = 0; it < 8; ++it) {
            int lin = tid + it * 256;
            int n  = lin >> 5;
            int d4 = lin & 31;
            float4 vv = *(const float4*)(v + (size_t)((b * L + c * 64 + n) * D) + d4 * 4);
            u32 h0, l0, h1, l1;
            split2(vv.x, vv.y, h0, l0);
            split2(vv.z, vv.w, h1, l1);
            *(uint2*)(sKh + n * 136 + d4 * 4) = make_uint2(h0, h1);
            *(uint2*)(sKl + n * 136 + d4 * 4) = make_uint2(l0, l1);
        }
        __syncthreads();

        // ---- O += E @ V, 3-pass bf16 split (warp w: d in [16w,16w+16)) ----
        #pragma unroll
        for (int kt2 = 0; kt2 < 4; ++kt2) {
            u32 ah0[4], al0[4], ah1[4], al1[4];
            LDSM4(ah0[0], ah0[1], ah0[2], ah0[3], aE + kt2 * 32);
            LDSM4(al0[0], al0[1], al0[2], al0[3], aE + 4608 + kt2 * 32);
            LDSM4(ah1[0], ah1[1], ah1[2], ah1[3], aE + 2304 + kt2 * 32);
            LDSM4(al1[0], al1[1], al1[2], al1[3], aE + 4608 + 2304 + kt2 * 32);
            #pragma unroll
            for (int dt = 0; dt < 2; ++dt) {
                u32 bh[2], bl[2];
                LDSM2T(bh[0], bh[1], aV + kt2 * 4352 + dt * 16);
                LDSM2T(bl[0], bl[1], aV + 17408 + kt2 * 4352 + dt * 16);
                MMAB(O[0][dt], ah0, bh[0], bh[1]);
                MMAB(O[0][dt], ah0, bl[0], bl[1]);
                MMAB(O[0][dt], al0, bh[0], bh[1]);
                MMAB(O[1][dt], ah1, bh[0], bh[1]);
                MMAB(O[1][dt], ah1, bl[0], bl[1]);
                MMAB(O[1][dt], al1, bh[0], bh[1]);
            }
        }
        __syncthreads();
    }

    // ---- cross-warp row sums ----
    #pragma unroll
    for (int rp = 0; rp < 4; ++rp) {
        float s = rsum[rp];
        s += __shfl_xor_sync(0xffffffffu, s, 1);
        s += __shfl_xor_sync(0xffffffffu, s, 2);
        if (tig == 0) sRS[(gid + 8 * rp) * 8 + wid] = s;
    }
    __syncthreads();
    float inv[4];
    #pragma unroll
    for (int rp = 0; rp < 4; ++rp) {
        const float* p = sRS + (gid + 8 * rp) * 8;
        inv[rp] = 1.0f / (p[0] + p[1] + p[2] + p[3] + p[4] + p[5] + p[6] + p[7]);
    }

    // ---- normalize attn in place (just-written -> L2 hits) ----
    #pragma unroll
    for (int rp = 0; rp < 4; ++rp) {
        float* arow = attn + (size_t)(b * L + m0 + gid + 8 * rp) * L;
        float iv = inv[rp];
        #pragma unroll
        for (int t = 0; t < 6; ++t) {
            float4* p = (float4*)arow + wid * 24 + tig * 6 + t;
            float4 vv = *p;
            vv.x *= iv; vv.y *= iv; vv.z *= iv; vv.w *= iv;
            *p = vv;
        }
    }

    // ---- normalized output ----
    #pragma unroll
    for (int mt = 0; mt < 2; ++mt)
        #pragma unroll
        for (int dt = 0; dt < 2; ++dt)
            #pragma unroll
            for (int h = 0; h < 2; ++h) {
                int rp = 2 * mt + h;
                int m  = gid + 8 * rp;
                float iv = inv[rp];
                float2 o = make_float2(O[mt][dt][2 * h] * iv, O[mt][dt][2 * h + 1] * iv);
                *(float2*)(out + (size_t)(b * L + m0 + m) * D + 16 * wid + 8 * dt + 2 * tig) = o;
            }
}

// ---------------------------------------------------------------------------
extern "C" void kernel_launch(void* const* d_in, const int* in_sizes, int n_in,
                              void* d_out, int out_size) {
    const float* q    = (const float*)d_in[0];
    const float* k    = (const float*)d_in[1];
    const float* v    = (const float*)d_in[2];
    const float* fc_w = (const float*)d_in[3];
    const float* fc_b = (const float*)d_in[4];

    float* out  = (float*)d_out;
    float* attn = out + (size_t)NB * L * D;

    lb_kernel<<<dim3(4, 4, NB), 256>>>(q, k, fc_w, fc_b);

    cudaFuncSetAttribute(fused_attn_kernel,
                         cudaFuncAttributeMaxDynamicSharedMemorySize, SMEM_BYTES);
    fused_attn_kernel<<<dim3(24, NB), 256, SMEM_BYTES>>>(q, k, v, out, attn);
}